// round 11
// baseline (speedup 1.0000x reference)
#include <cuda_runtime.h>
#include <cuda_bf16.h>
#include <math.h>
#include <stdint.h>

// Problem constants
#define GN 100000
#define GE 1600000
#define D  128
#define DOUT 64

// ---------------- static device scratch --------------------------------------
__device__ __nv_bfloat16 g_aggHi[(size_t)GN * D];
__device__ __nv_bfloat16 g_aggLo[(size_t)GN * D];
__device__ float g_xA[(size_t)GN * D];
__device__ float g_xB[(size_t)GN * D];
__device__ int   g_deg[GN];
__device__ int   g_rowptr[GN + 1];
__device__ int   g_csrsrc[GE];
__device__ int   g_bsum[128];
__device__ int   g_bsumScan[128];
// transposed bf16 weights Bt[n][k]: 5 x [128][128] + 1 x [64][128]
__device__ __nv_bfloat16 g_wtHi[5 * 16384 + 8192];
__device__ __nv_bfloat16 g_wtLo[5 * 16384 + 8192];

// ---------------- helpers -----------------------------------------------------
__device__ __forceinline__ uint32_t smem_u32(const void* p) {
    uint32_t a;
    asm("{ .reg .u64 t; cvta.to.shared.u64 t, %1; cvt.u32.u64 %0, t; }" : "=r"(a) : "l"(p));
    return a;
}
__device__ __forceinline__ void ldsm_x4(uint32_t* r, uint32_t addr) {
    asm volatile("ldmatrix.sync.aligned.m8n8.x4.shared.b16 {%0,%1,%2,%3}, [%4];"
        : "=r"(r[0]), "=r"(r[1]), "=r"(r[2]), "=r"(r[3]) : "r"(addr));
}
__device__ __forceinline__ void mma16816(float* d, const uint32_t* a, const uint32_t* b) {
    asm volatile(
        "mma.sync.aligned.m16n8k16.row.col.f32.bf16.bf16.f32 "
        "{%0,%1,%2,%3}, {%4,%5,%6,%7}, {%8,%9}, {%0,%1,%2,%3};"
        : "+f"(d[0]), "+f"(d[1]), "+f"(d[2]), "+f"(d[3])
        : "r"(a[0]), "r"(a[1]), "r"(a[2]), "r"(a[3]), "r"(b[0]), "r"(b[1]));
}
__device__ __forceinline__ void cp_async16(uint32_t smem_addr, const void* gptr, int szfill) {
    asm volatile("cp.async.cg.shared.global [%0], [%1], 16, %2;"
        :: "r"(smem_addr), "l"(gptr), "r"(szfill) : "memory");
}
__device__ __forceinline__ void cp_commit() {
    asm volatile("cp.async.commit_group;" ::: "memory");
}
template<int N>
__device__ __forceinline__ void cp_wait() {
    asm volatile("cp.async.wait_group %0;" :: "n"(N) : "memory");
}
// PDL: release dependents early / wait on upstream grid
__device__ __forceinline__ void pdl_trigger() {
    asm volatile("griddepcontrol.launch_dependents;");
}
__device__ __forceinline__ void pdl_wait() {
    asm volatile("griddepcontrol.wait;" ::: "memory");
}

// ---------------- CSR build ---------------------------------------------------
__global__ void count_deg_kernel(const int4* __restrict__ dst4) {
    int e = blockIdx.x * blockDim.x + threadIdx.x;
    if (e < GE / 4) {
        int4 d = dst4[e];
        atomicAdd(&g_deg[d.x], 1);
        atomicAdd(&g_deg[d.y], 1);
        atomicAdd(&g_deg[d.z], 1);
        atomicAdd(&g_deg[d.w], 1);
    }
}
__global__ void scan1_kernel() {   // grid 98, block 1024
    __shared__ int s[1024];
    const int t = threadIdx.x;
    int i = blockIdx.x * 1024 + t;
    int v = (i < GN) ? g_deg[i] : 0;
    s[t] = v;
    __syncthreads();
#pragma unroll
    for (int off = 1; off < 1024; off <<= 1) {
        int add = (t >= off) ? s[t - off] : 0;
        __syncthreads();
        s[t] += add;
        __syncthreads();
    }
    if (i < GN) g_rowptr[i] = s[t] - v;   // block-local exclusive
    if (t == 1023) g_bsum[blockIdx.x] = s[t];
}
__global__ void scan2_kernel() {   // 1 block, 128 threads
    __shared__ int s[128];
    const int t = threadIdx.x;
    int v = (t < 98) ? g_bsum[t] : 0;
    s[t] = v;
    __syncthreads();
#pragma unroll
    for (int off = 1; off < 128; off <<= 1) {
        int add = (t >= off) ? s[t - off] : 0;
        __syncthreads();
        s[t] += add;
        __syncthreads();
    }
    g_bsumScan[t] = s[t] - v;
}
__global__ void scan3_kernel() {   // grid 98, block 1024
    int i = blockIdx.x * 1024 + threadIdx.x;
    if (i < GN) g_rowptr[i] += g_bsumScan[blockIdx.x];
}
// fill bumps rowptr itself: afterwards rowptr[i] == end(i) (shifted CSR)
__global__ void fill_csr_kernel(const int2* __restrict__ src2,
                                const int2* __restrict__ dst2) {
    pdl_trigger();   // agg0 may prelaunch; it only touches x before its wait
    int e = blockIdx.x * blockDim.x + threadIdx.x;
    if (e < GE / 2) {
        int2 sv = src2[e];
        int2 dv = dst2[e];
        int p0 = atomicAdd(&g_rowptr[dv.x], 1);
        g_csrsrc[p0] = sv.x;
        int p1 = atomicAdd(&g_rowptr[dv.y], 1);
        g_csrsrc[p1] = sv.y;
    }
}

// ---------------- merged weight convert+transpose -----------------------------
struct WPtrs { const float* w[6]; };
__global__ void convw_all_kernel(WPtrs p,
                                 __nv_bfloat16* __restrict__ oh,
                                 __nv_bfloat16* __restrict__ ol) {
    int bid = blockIdx.x;
    int li, n, Nw;
    if (bid < 640) { li = bid >> 7; n = bid & 127; Nw = 128; }
    else           { li = 5;        n = bid - 640; Nw = 64; }
    int k = threadIdx.x;
    float v = p.w[li][(size_t)k * Nw + n];
    __nv_bfloat16 h = __float2bfloat16_rn(v);
    float lo = v - __bfloat162float(h);
    oh[li * 16384 + n * 128 + k] = h;
    ol[li * 16384 + n * 128 + k] = __float2bfloat16_rn(lo);
}

// ---------------- aggregation (shifted CSR): agg[i] = x[i] + sum nbrs ---------
// SELF_SAFE: x readable before upstream completes (layer 0: upstream is CSR fill)
template<bool SELF_SAFE>
__global__ void agg_kernel(const float* __restrict__ x,
                           __nv_bfloat16* __restrict__ aggHi,
                           __nv_bfloat16* __restrict__ aggLo) {
    pdl_trigger();   // downstream MLP prelaunches; pre-wait it reads only weights
    int gi = blockIdx.x * blockDim.x + threadIdx.x;
    int node = gi >> 5;
    int lane = gi & 31;
    if (node >= GN) { pdl_wait(); return; }
    const float4* x4 = (const float4*)x;
    float4 acc;
    int s, e;
    if (SELF_SAFE) {
        acc = x4[(size_t)node * 32 + lane];   // x safe vs fill
        pdl_wait();                            // CSR now valid
        s = node ? __ldg(&g_rowptr[node - 1]) : 0;
        e = __ldg(&g_rowptr[node]);
    } else {
        s = node ? __ldg(&g_rowptr[node - 1]) : 0;  // CSR safe vs MLP
        e = __ldg(&g_rowptr[node]);
        pdl_wait();                            // x (MLP output) now valid
        acc = x4[(size_t)node * 32 + lane];
    }
    int i = s;
    int sr = (i < e) ? __ldg(&g_csrsrc[i]) : 0;
    for (; i < e; i++) {
        int srn = (i + 1 < e) ? __ldg(&g_csrsrc[i + 1]) : 0;
        float4 v = x4[(size_t)sr * 32 + lane];
        acc.x += v.x; acc.y += v.y; acc.z += v.z; acc.w += v.w;
        sr = srn;
    }
    __nv_bfloat162 h0 = __floats2bfloat162_rn(acc.x, acc.y);
    __nv_bfloat162 h1 = __floats2bfloat162_rn(acc.z, acc.w);
    __nv_bfloat162 l0 = __floats2bfloat162_rn(acc.x - __bfloat162float(h0.x),
                                              acc.y - __bfloat162float(h0.y));
    __nv_bfloat162 l1 = __floats2bfloat162_rn(acc.z - __bfloat162float(h1.x),
                                              acc.w - __bfloat162float(h1.y));
    union U { uint2 u; __nv_bfloat162 h[2]; } uh, ul;
    uh.h[0] = h0; uh.h[1] = h1;
    ul.h[0] = l0; ul.h[1] = l1;
    ((uint2*)aggHi)[(size_t)node * 32 + lane] = uh.u;
    ((uint2*)aggLo)[(size_t)node * 32 + lane] = ul.u;
}

// ---------------- fused MLP: (agg @ W1 + b1).relu() @ W2 + b2 + epilogue -------
// GEMM1: A[256,128] @ W1^T -> h (stays in smem, bias+relu+bf16-split applied)
// GEMM2: h @ W2^T  -> epilogue
// EPI 1: relu(bn(v+b2)) + resid -> fp32 [M,128]
// EPI 2: log_softmax(v+b2) -> fp32 [M,64]  (fused via smem staging)
template<int NB2, int EPI>
__global__ __launch_bounds__(256, 1) void mlp_fused_kernel(
    const __nv_bfloat16* __restrict__ Ahi, const __nv_bfloat16* __restrict__ Alo,
    const __nv_bfloat16* __restrict__ B1hi, const __nv_bfloat16* __restrict__ B1lo,
    const __nv_bfloat16* __restrict__ B2hi, const __nv_bfloat16* __restrict__ B2lo,
    const float* __restrict__ bias1, const float* __restrict__ bias2,
    const float* __restrict__ gam, const float* __restrict__ bet,
    const float* __restrict__ mean, const float* __restrict__ var,
    const float* __restrict__ resid,
    float* __restrict__ outF, int M)
{
    extern __shared__ char smem[];
    constexpr int BM   = 256;
    constexpr int ROWB = 272;                 // 256B row + 16B pad
    constexpr int SM_PAR  = 0;                // b1[128], b2/sc/sh[128 each]
    constexpr int SM_A_HI = 2048;             // A tile, later h tile (hi)
    constexpr int SM_A_LO = SM_A_HI + BM * ROWB;
    constexpr int SM_B_HI = SM_A_LO + BM * ROWB;   // W1 then W2 (hi); later lsm stage
    constexpr int SM_B_LO = SM_B_HI + 128 * ROWB;
    constexpr int MI   = 4;                   // 4 x m16 = 64 rows per warp
    constexpr int NAT1 = 8;                   // GEMM1: WN=64
    constexpr int WN2  = NB2 / 2;
    constexpr int NAT2 = WN2 / 8;
    constexpr int LSTR = 65;                  // lsm staging row stride (floats)

    pdl_trigger();   // next agg prelaunches; pre-wait it reads only CSR

    const uint32_t sb = smem_u32(smem);
    const int tid = threadIdx.x;
    const int wid = tid >> 5;
    const int lid = tid & 31;
    const int blockRow = blockIdx.x * BM;

    float* sB1 = (float*)(smem + SM_PAR);
    float* sB2 = sB1 + 128;
    float* sSc = sB2 + 128;
    float* sSh = sSc + 128;
    if (tid < 128) sB1[tid] = bias1[tid];
    if (tid < NB2) {
        sB2[tid] = bias2[tid];
        if (EPI == 1) {
            float s = gam[tid] * rsqrtf(var[tid] + 1e-5f);
            sSc[tid] = s;
            sSh[tid] = bet[tid] - mean[tid] * s;
        }
    }

    // ---- W1 cp.async FIRST (weights are safe pre-wait) — group 0 --------------
    const uint4* B1hiG = (const uint4*)B1hi;
    const uint4* B1loG = (const uint4*)B1lo;
    for (int idx = tid; idx < 128 * 16; idx += 256) {
        int r = idx >> 4, c = idx & 15;
        cp_async16(sb + SM_B_HI + r * ROWB + c * 16, B1hiG + (size_t)r * 16 + c, 16);
        cp_async16(sb + SM_B_LO + r * ROWB + c * 16, B1loG + (size_t)r * 16 + c, 16);
    }
    cp_commit();   // group 0: W1

    pdl_wait();    // upstream agg output (A tile source) now valid

    // ---- A tile, two K-halves — groups 1, 2 -----------------------------------
    const uint4* AhiG = (const uint4*)Ahi;
    const uint4* AloG = (const uint4*)Alo;
#pragma unroll
    for (int h = 0; h < 2; h++) {
        for (int idx = tid; idx < BM * 8; idx += 256) {
            int r = idx >> 3, c = (idx & 7) + h * 8;
            int gr = blockRow + r;
            int zf = (gr < M) ? 16 : 0;
            int grc = (gr < M) ? gr : 0;
            cp_async16(sb + SM_A_HI + r * ROWB + c * 16, AhiG + (size_t)grc * 16 + c, zf);
            cp_async16(sb + SM_A_LO + r * ROWB + c * 16, AloG + (size_t)grc * 16 + c, zf);
        }
        cp_commit();
    }

    const int wm = wid & 3;              // 4 warp-rows x 64
    const int wn = wid >> 2;             // 2 warp-cols
    const int m0 = wm * 64;
    const int n0 = wn * 64;              // GEMM1 warp col base
    const int n02 = wn * WN2;            // GEMM2 warp col base

    const uint32_t aRow = (uint32_t)(lid & 15);
    const uint32_t aK   = (uint32_t)((lid >> 4) << 3);
    const uint32_t bN   = (uint32_t)((lid & 7) + ((lid >> 4) << 3));
    const uint32_t bK   = (uint32_t)(((lid >> 3) & 1) << 3);

    const uint32_t aHi0 = sb + SM_A_HI + (m0 + aRow) * ROWB + aK * 2;
    const uint32_t aLo0 = sb + SM_A_LO + (m0 + aRow) * ROWB + aK * 2;
    const uint32_t bHi1 = sb + SM_B_HI + (n0 + bN) * ROWB + bK * 2;
    const uint32_t bLo1 = sb + SM_B_LO + (n0 + bN) * ROWB + bK * 2;

    const int qr = lid >> 2;
    const int qc = (lid & 3) * 2;

    // ================= GEMM 1 =================
    float acc[MI][NAT1][4];
#pragma unroll
    for (int i = 0; i < MI; i++)
#pragma unroll
        for (int j = 0; j < NAT1; j++)
#pragma unroll
            for (int q = 0; q < 4; q++) acc[i][j][q] = 0.f;

#pragma unroll
    for (int half = 0; half < 2; half++) {
        if (half == 0) { cp_wait<1>(); } else { cp_wait<0>(); }
        __syncthreads();
#pragma unroll
        for (int ks = half * 4; ks < half * 4 + 4; ks++) {
            const uint32_t kb = (uint32_t)ks * 32;
            uint32_t ah[MI][4];
#pragma unroll
            for (int mi = 0; mi < MI; mi++)
                ldsm_x4(ah[mi], aHi0 + mi * 16 * ROWB + kb);
            uint32_t bh[NAT1][2], bl[NAT1][2];
#pragma unroll
            for (int jj = 0; jj < NAT1 / 2; jj++) {
                uint32_t r4[4];
                ldsm_x4(r4, bHi1 + jj * 16 * ROWB + kb);
                bh[2 * jj][0] = r4[0]; bh[2 * jj][1] = r4[1];
                bh[2 * jj + 1][0] = r4[2]; bh[2 * jj + 1][1] = r4[3];
                ldsm_x4(r4, bLo1 + jj * 16 * ROWB + kb);
                bl[2 * jj][0] = r4[0]; bl[2 * jj][1] = r4[1];
                bl[2 * jj + 1][0] = r4[2]; bl[2 * jj + 1][1] = r4[3];
            }
#pragma unroll
            for (int mi = 0; mi < MI; mi++)
#pragma unroll
                for (int j = 0; j < NAT1; j++) {
                    mma16816(acc[mi][j], ah[mi], bh[j]);
                    mma16816(acc[mi][j], ah[mi], bl[j]);
                }
            uint32_t al[MI][4];
#pragma unroll
            for (int mi = 0; mi < MI; mi++)
                ldsm_x4(al[mi], aLo0 + mi * 16 * ROWB + kb);
#pragma unroll
            for (int mi = 0; mi < MI; mi++)
#pragma unroll
                for (int j = 0; j < NAT1; j++)
                    mma16816(acc[mi][j], al[mi], bh[j]);
        }
    }
    __syncthreads();   // everyone done reading A and W1 smem

    // ---- load W2 into B region (overwrites W1) while we write h ---------------
    const uint4* B2hiG = (const uint4*)B2hi;
    const uint4* B2loG = (const uint4*)B2lo;
    for (int idx = tid; idx < NB2 * 16; idx += 256) {
        int r = idx >> 4, c = idx & 15;
        cp_async16(sb + SM_B_HI + r * ROWB + c * 16, B2hiG + (size_t)r * 16 + c, 16);
        cp_async16(sb + SM_B_LO + r * ROWB + c * 16, B2loG + (size_t)r * 16 + c, 16);
    }
    cp_commit();

    // ---- epilogue 1: h = relu(acc + b1), bf16-split, into A smem region -------
#pragma unroll
    for (int i = 0; i < MI; i++) {
        const int rl = m0 + i * 16 + qr;
#pragma unroll
        for (int j = 0; j < NAT1; j++) {
            const int col = n0 + j * 8 + qc;
            float t0 = fmaxf(acc[i][j][0] + sB1[col], 0.f);
            float t1 = fmaxf(acc[i][j][1] + sB1[col + 1], 0.f);
            float t2 = fmaxf(acc[i][j][2] + sB1[col], 0.f);
            float t3 = fmaxf(acc[i][j][3] + sB1[col + 1], 0.f);
            __nv_bfloat162 hh = __floats2bfloat162_rn(t0, t1);
            __nv_bfloat162 ll = __floats2bfloat162_rn(
                t0 - __bfloat162float(hh.x), t1 - __bfloat162float(hh.y));
            *(__nv_bfloat162*)(smem + SM_A_HI + rl * ROWB + col * 2) = hh;
            *(__nv_bfloat162*)(smem + SM_A_LO + rl * ROWB + col * 2) = ll;
            hh = __floats2bfloat162_rn(t2, t3);
            ll = __floats2bfloat162_rn(
                t2 - __bfloat162float(hh.x), t3 - __bfloat162float(hh.y));
            *(__nv_bfloat162*)(smem + SM_A_HI + (rl + 8) * ROWB + col * 2) = hh;
            *(__nv_bfloat162*)(smem + SM_A_LO + (rl + 8) * ROWB + col * 2) = ll;
        }
    }
    cp_wait<0>();
    __syncthreads();   // h writes + W2 arrival visible to all

    // ================= GEMM 2 =================
    float acc2[MI][NAT2][4];
#pragma unroll
    for (int i = 0; i < MI; i++)
#pragma unroll
        for (int j = 0; j < NAT2; j++)
#pragma unroll
            for (int q = 0; q < 4; q++) acc2[i][j][q] = 0.f;

    const uint32_t bHi2 = sb + SM_B_HI + (n02 + bN) * ROWB + bK * 2;
    const uint32_t bLo2 = sb + SM_B_LO + (n02 + bN) * ROWB + bK * 2;

#pragma unroll
    for (int ks = 0; ks < 8; ks++) {
        const uint32_t kb = (uint32_t)ks * 32;
        uint32_t ah[MI][4];
#pragma unroll
        for (int mi = 0; mi < MI; mi++)
            ldsm_x4(ah[mi], aHi0 + mi * 16 * ROWB + kb);
        uint32_t bh[NAT2][2], bl[NAT2][2];
#pragma unroll
        for (int jj = 0; jj < NAT2 / 2; jj++) {
            uint32_t r4[4];
            ldsm_x4(r4, bHi2 + jj * 16 * ROWB + kb);
            bh[2 * jj][0] = r4[0]; bh[2 * jj][1] = r4[1];
            bh[2 * jj + 1][0] = r4[2]; bh[2 * jj + 1][1] = r4[3];
            ldsm_x4(r4, bLo2 + jj * 16 * ROWB + kb);
            bl[2 * jj][0] = r4[0]; bl[2 * jj][1] = r4[1];
            bl[2 * jj + 1][0] = r4[2]; bl[2 * jj + 1][1] = r4[3];
        }
#pragma unroll
        for (int mi = 0; mi < MI; mi++)
#pragma unroll
            for (int j = 0; j < NAT2; j++) {
                mma16816(acc2[mi][j], ah[mi], bh[j]);
                mma16816(acc2[mi][j], ah[mi], bl[j]);
            }
        uint32_t al[MI][4];
#pragma unroll
        for (int mi = 0; mi < MI; mi++)
            ldsm_x4(al[mi], aLo0 + mi * 16 * ROWB + kb);
#pragma unroll
        for (int mi = 0; mi < MI; mi++)
#pragma unroll
            for (int j = 0; j < NAT2; j++)
                mma16816(acc2[mi][j], al[mi], bh[j]);
    }

    // ---- epilogue 2 ------------------------------------------------------------
    if (EPI == 1) {
#pragma unroll
        for (int i = 0; i < MI; i++) {
            const int r0 = blockRow + m0 + i * 16 + qr;   // rows r0, r0+8
#pragma unroll
            for (int j = 0; j < NAT2; j++) {
                const int col = n02 + j * 8 + qc;
                float t0 = acc2[i][j][0] + sB2[col];
                float t1 = acc2[i][j][1] + sB2[col + 1];
                float t2 = acc2[i][j][2] + sB2[col];
                float t3 = acc2[i][j][3] + sB2[col + 1];
                float sc0 = sSc[col], sc1 = sSc[col + 1];
                float sh0 = sSh[col], sh1 = sSh[col + 1];
                t0 = fmaxf(fmaf(t0, sc0, sh0), 0.f);
                t1 = fmaxf(fmaf(t1, sc1, sh1), 0.f);
                t2 = fmaxf(fmaf(t2, sc0, sh0), 0.f);
                t3 = fmaxf(fmaf(t3, sc1, sh1), 0.f);
                if (r0 < M) {
                    float2 rr = *(const float2*)(resid + (size_t)r0 * 128 + col);
                    *(float2*)(outF + (size_t)r0 * 128 + col) =
                        make_float2(t0 + rr.x, t1 + rr.y);
                }
                if (r0 + 8 < M) {
                    float2 rr = *(const float2*)(resid + (size_t)(r0 + 8) * 128 + col);
                    *(float2*)(outF + (size_t)(r0 + 8) * 128 + col) =
                        make_float2(t2 + rr.x, t3 + rr.y);
                }
            }
        }
    } else {
        // fused log_softmax: stage v into smem (reuse B region), reduce per row
        float* sL = (float*)(smem + SM_B_HI);
        __syncthreads();   // all GEMM2 B reads done before overwrite
#pragma unroll
        for (int i = 0; i < MI; i++) {
            const int rl = m0 + i * 16 + qr;
#pragma unroll
            for (int j = 0; j < NAT2; j++) {
                const int col = n02 + j * 8 + qc;
                sL[rl * LSTR + col]           = acc2[i][j][0] + sB2[col];
                sL[rl * LSTR + col + 1]       = acc2[i][j][1] + sB2[col + 1];
                sL[(rl + 8) * LSTR + col]     = acc2[i][j][2] + sB2[col];
                sL[(rl + 8) * LSTR + col + 1] = acc2[i][j][3] + sB2[col + 1];
            }
        }
        __syncthreads();
        const int grow = blockRow + tid;   // one thread per row
        if (grow < M) {
            float v[64];
            const float* row = sL + tid * LSTR;
#pragma unroll
            for (int c = 0; c < 64; c++) v[c] = row[c];
            float m = v[0];
#pragma unroll
            for (int c = 1; c < 64; c++) m = fmaxf(m, v[c]);
            float s = 0.f;
#pragma unroll
            for (int c = 0; c < 64; c++) s += expf(v[c] - m);
            float l = m + logf(s);
            float4* o4 = (float4*)(outF + (size_t)grow * 64);
#pragma unroll
            for (int q = 0; q < 16; q++)
                o4[q] = make_float4(v[4 * q] - l, v[4 * q + 1] - l,
                                    v[4 * q + 2] - l, v[4 * q + 3] - l);
        }
    }
}

// ---------------- launch ------------------------------------------------------
static inline int smem_total() {
    // params + A(2x 256x272) + B(2x 128x272)
    return 2048 + 2 * 256 * 272 + 2 * 128 * 272;
}

extern "C" void kernel_launch(void* const* d_in, const int* in_sizes, int n_in,
                              void* d_out, int out_size) {
    const float* x  = (const float*)d_in[0];
    const int*   ei = (const int*)d_in[1];
    const float* W1[3] = {(const float*)d_in[2],  (const float*)d_in[6],  (const float*)d_in[10]};
    const float* b1[3] = {(const float*)d_in[3],  (const float*)d_in[7],  (const float*)d_in[11]};
    const float* W2[3] = {(const float*)d_in[4],  (const float*)d_in[8],  (const float*)d_in[12]};
    const float* b2[3] = {(const float*)d_in[5],  (const float*)d_in[9],  (const float*)d_in[13]};
    const float* gg[2] = {(const float*)d_in[14], (const float*)d_in[18]};
    const float* be[2] = {(const float*)d_in[15], (const float*)d_in[19]};
    const float* mm[2] = {(const float*)d_in[16], (const float*)d_in[20]};
    const float* vv[2] = {(const float*)d_in[17], (const float*)d_in[21]};

    const int* src = ei;
    const int* dst = ei + GE;
    float* out = (float*)d_out;

    __nv_bfloat16 *aggHi, *aggLo, *wHi, *wLo;
    float *xA, *xB;
    int* degPtr;
    cudaGetSymbolAddress((void**)&aggHi, g_aggHi);
    cudaGetSymbolAddress((void**)&aggLo, g_aggLo);
    cudaGetSymbolAddress((void**)&wHi, g_wtHi);
    cudaGetSymbolAddress((void**)&wLo, g_wtLo);
    cudaGetSymbolAddress((void**)&xA, g_xA);
    cudaGetSymbolAddress((void**)&xB, g_xB);
    cudaGetSymbolAddress((void**)&degPtr, g_deg);

    const int SMT = smem_total();
    cudaFuncSetAttribute(mlp_fused_kernel<128, 1>,
                         cudaFuncAttributeMaxDynamicSharedMemorySize, SMT);
    cudaFuncSetAttribute(mlp_fused_kernel<64, 2>,
                         cudaFuncAttributeMaxDynamicSharedMemorySize, SMT);

    const int M = GN;
    const int gemmGrid = (GN + 255) / 256;           // 391
    const int warpGrid = (GN * 32 + 255) / 256;      // 12500
    const int SCAN_BLKS = (GN + 1023) / 1024;        // 98

    // PDL launch config (programmatic stream serialization)
    cudaLaunchAttribute pdlAttr[1];
    pdlAttr[0].id = cudaLaunchAttributeProgrammaticStreamSerialization;
    pdlAttr[0].val.programmaticStreamSerializationAllowed = 1;
    cudaLaunchConfig_t cfgAgg = {};
    cfgAgg.gridDim = dim3(warpGrid); cfgAgg.blockDim = dim3(256);
    cfgAgg.dynamicSmemBytes = 0; cfgAgg.stream = 0;
    cfgAgg.attrs = pdlAttr; cfgAgg.numAttrs = 1;
    cudaLaunchConfig_t cfgMlp = {};
    cfgMlp.gridDim = dim3(gemmGrid); cfgMlp.blockDim = dim3(256);
    cfgMlp.dynamicSmemBytes = SMT; cfgMlp.stream = 0;
    cfgMlp.attrs = pdlAttr; cfgMlp.numAttrs = 1;

    // Weight prep (single merged kernel)
    WPtrs wp;
    wp.w[0] = W1[0]; wp.w[1] = W2[0]; wp.w[2] = W1[1];
    wp.w[3] = W2[1]; wp.w[4] = W1[2]; wp.w[5] = W2[2];
    convw_all_kernel<<<704, 128>>>(wp, wHi, wLo);

    // CSR build (reused for all 3 layers; rowptr left shifted by fill)
    cudaMemsetAsync(degPtr, 0, GN * sizeof(int));
    count_deg_kernel<<<(GE / 4 + 255) / 256, 256>>>((const int4*)dst);
    scan1_kernel<<<SCAN_BLKS, 1024>>>();
    scan2_kernel<<<1, 128>>>();
    scan3_kernel<<<SCAN_BLKS, 1024>>>();
    fill_csr_kernel<<<(GE / 2 + 255) / 256, 256>>>((const int2*)src, (const int2*)dst);

    // Layer 0 (agg0 may prelaunch into fill's tail; self rows of x are safe)
    cudaLaunchKernelEx(&cfgAgg, agg_kernel<true>, x, aggHi, aggLo);
    cudaLaunchKernelEx(&cfgMlp, mlp_fused_kernel<128, 1>,
        (const __nv_bfloat16*)aggHi, (const __nv_bfloat16*)aggLo,
        (const __nv_bfloat16*)(wHi + 0 * 16384), (const __nv_bfloat16*)(wLo + 0 * 16384),
        (const __nv_bfloat16*)(wHi + 1 * 16384), (const __nv_bfloat16*)(wLo + 1 * 16384),
        b1[0], b2[0], gg[0], be[0], mm[0], vv[0], x, (float*)xA, M);

    // Layer 1
    cudaLaunchKernelEx(&cfgAgg, agg_kernel<false>, (const float*)xA, aggHi, aggLo);
    cudaLaunchKernelEx(&cfgMlp, mlp_fused_kernel<128, 1>,
        (const __nv_bfloat16*)aggHi, (const __nv_bfloat16*)aggLo,
        (const __nv_bfloat16*)(wHi + 2 * 16384), (const __nv_bfloat16*)(wLo + 2 * 16384),
        (const __nv_bfloat16*)(wHi + 3 * 16384), (const __nv_bfloat16*)(wLo + 3 * 16384),
        b1[1], b2[1], gg[1], be[1], mm[1], vv[1], (const float*)xA, (float*)xB, M);

    // Layer 2 (final conv + fused log_softmax)
    cudaLaunchKernelEx(&cfgAgg, agg_kernel<false>, (const float*)xB, aggHi, aggLo);
    cudaLaunchKernelEx(&cfgMlp, mlp_fused_kernel<64, 2>,
        (const __nv_bfloat16*)aggHi, (const __nv_bfloat16*)aggLo,
        (const __nv_bfloat16*)(wHi + 4 * 16384), (const __nv_bfloat16*)(wLo + 4 * 16384),
        (const __nv_bfloat16*)(wHi + 5 * 16384), (const __nv_bfloat16*)(wLo + 5 * 16384),
        b1[2], b2[2], (const float*)nullptr, (const float*)nullptr,
        (const float*)nullptr, (const float*)nullptr, (const float*)nullptr, out, M);
}

// round 12
// speedup vs baseline: 1.0280x; 1.0280x over previous
#include <cuda_runtime.h>
#include <cuda_bf16.h>
#include <math.h>
#include <stdint.h>

// Problem constants
#define GN 100000
#define GE 1600000
#define D  128
#define DOUT 64

// ---------------- static device scratch --------------------------------------
__device__ __nv_bfloat16 g_aggHi[(size_t)GN * D];
__device__ __nv_bfloat16 g_aggLo[(size_t)GN * D];
__device__ float g_xA[(size_t)GN * D];
__device__ float g_xB[(size_t)GN * D];
__device__ int   g_deg[GN];
__device__ int   g_rowptr[GN + 1];
__device__ int   g_csrsrc[GE];
__device__ int   g_bsum[128];
__device__ int   g_bsumScan[128];
// transposed bf16 weights Bt[n][k]: 5 x [128][128] + 1 x [64][128]
__device__ __nv_bfloat16 g_wtHi[5 * 16384 + 8192];
__device__ __nv_bfloat16 g_wtLo[5 * 16384 + 8192];

// ---------------- helpers -----------------------------------------------------
__device__ __forceinline__ uint32_t smem_u32(const void* p) {
    uint32_t a;
    asm("{ .reg .u64 t; cvta.to.shared.u64 t, %1; cvt.u32.u64 %0, t; }" : "=r"(a) : "l"(p));
    return a;
}
__device__ __forceinline__ void ldsm_x4(uint32_t* r, uint32_t addr) {
    asm volatile("ldmatrix.sync.aligned.m8n8.x4.shared.b16 {%0,%1,%2,%3}, [%4];"
        : "=r"(r[0]), "=r"(r[1]), "=r"(r[2]), "=r"(r[3]) : "r"(addr));
}
__device__ __forceinline__ void mma16816(float* d, const uint32_t* a, const uint32_t* b) {
    asm volatile(
        "mma.sync.aligned.m16n8k16.row.col.f32.bf16.bf16.f32 "
        "{%0,%1,%2,%3}, {%4,%5,%6,%7}, {%8,%9}, {%0,%1,%2,%3};"
        : "+f"(d[0]), "+f"(d[1]), "+f"(d[2]), "+f"(d[3])
        : "r"(a[0]), "r"(a[1]), "r"(a[2]), "r"(a[3]), "r"(b[0]), "r"(b[1]));
}
__device__ __forceinline__ void cp_async16(uint32_t smem_addr, const void* gptr, int szfill) {
    asm volatile("cp.async.cg.shared.global [%0], [%1], 16, %2;"
        :: "r"(smem_addr), "l"(gptr), "r"(szfill) : "memory");
}
__device__ __forceinline__ void cp_commit() {
    asm volatile("cp.async.commit_group;" ::: "memory");
}
template<int N>
__device__ __forceinline__ void cp_wait() {
    asm volatile("cp.async.wait_group %0;" :: "n"(N) : "memory");
}

// ---------------- CSR build ---------------------------------------------------
__global__ void count_deg_kernel(const int4* __restrict__ dst4) {
    int e = blockIdx.x * blockDim.x + threadIdx.x;
    if (e < GE / 4) {
        int4 d = dst4[e];
        atomicAdd(&g_deg[d.x], 1);
        atomicAdd(&g_deg[d.y], 1);
        atomicAdd(&g_deg[d.z], 1);
        atomicAdd(&g_deg[d.w], 1);
    }
}
__global__ void scan1_kernel() {   // grid 98, block 1024
    __shared__ int s[1024];
    const int t = threadIdx.x;
    int i = blockIdx.x * 1024 + t;
    int v = (i < GN) ? g_deg[i] : 0;
    s[t] = v;
    __syncthreads();
#pragma unroll
    for (int off = 1; off < 1024; off <<= 1) {
        int add = (t >= off) ? s[t - off] : 0;
        __syncthreads();
        s[t] += add;
        __syncthreads();
    }
    if (i < GN) g_rowptr[i] = s[t] - v;   // block-local exclusive
    if (t == 1023) g_bsum[blockIdx.x] = s[t];
}
__global__ void scan2_kernel() {   // 1 block, 128 threads
    __shared__ int s[128];
    const int t = threadIdx.x;
    int v = (t < 98) ? g_bsum[t] : 0;
    s[t] = v;
    __syncthreads();
#pragma unroll
    for (int off = 1; off < 128; off <<= 1) {
        int add = (t >= off) ? s[t - off] : 0;
        __syncthreads();
        s[t] += add;
        __syncthreads();
    }
    g_bsumScan[t] = s[t] - v;
}
__global__ void scan3_kernel() {   // grid 98, block 1024
    int i = blockIdx.x * 1024 + threadIdx.x;
    if (i < GN) g_rowptr[i] += g_bsumScan[blockIdx.x];
}
// fill bumps rowptr itself: afterwards rowptr[i] == end(i) (shifted CSR)
__global__ void fill_csr_kernel(const int2* __restrict__ src2,
                                const int2* __restrict__ dst2) {
    int e = blockIdx.x * blockDim.x + threadIdx.x;
    if (e < GE / 2) {
        int2 sv = src2[e];
        int2 dv = dst2[e];
        int p0 = atomicAdd(&g_rowptr[dv.x], 1);
        g_csrsrc[p0] = sv.x;
        int p1 = atomicAdd(&g_rowptr[dv.y], 1);
        g_csrsrc[p1] = sv.y;
    }
}

// ---------------- merged weight convert+transpose -----------------------------
struct WPtrs { const float* w[6]; };
__global__ void convw_all_kernel(WPtrs p,
                                 __nv_bfloat16* __restrict__ oh,
                                 __nv_bfloat16* __restrict__ ol) {
    int bid = blockIdx.x;
    int li, n, Nw;
    if (bid < 640) { li = bid >> 7; n = bid & 127; Nw = 128; }
    else           { li = 5;        n = bid - 640; Nw = 64; }
    int k = threadIdx.x;
    float v = p.w[li][(size_t)k * Nw + n];
    __nv_bfloat16 h = __float2bfloat16_rn(v);
    float lo = v - __bfloat162float(h);
    oh[li * 16384 + n * 128 + k] = h;
    ol[li * 16384 + n * 128 + k] = __float2bfloat16_rn(lo);
}

// ---------------- aggregation (shifted CSR): agg[i] = x[i] + sum nbrs ---------
__global__ void agg_kernel(const float* __restrict__ x,
                           __nv_bfloat16* __restrict__ aggHi,
                           __nv_bfloat16* __restrict__ aggLo) {
    int gi = blockIdx.x * blockDim.x + threadIdx.x;
    int node = gi >> 5;
    int lane = gi & 31;
    if (node >= GN) return;
    const float4* x4 = (const float4*)x;
    float4 acc = x4[(size_t)node * 32 + lane];
    int s = node ? __ldg(&g_rowptr[node - 1]) : 0;
    int e = __ldg(&g_rowptr[node]);
    int i = s;
    int sr = (i < e) ? __ldg(&g_csrsrc[i]) : 0;
    for (; i < e; i++) {
        int srn = (i + 1 < e) ? __ldg(&g_csrsrc[i + 1]) : 0;
        float4 v = x4[(size_t)sr * 32 + lane];
        acc.x += v.x; acc.y += v.y; acc.z += v.z; acc.w += v.w;
        sr = srn;
    }
    __nv_bfloat162 h0 = __floats2bfloat162_rn(acc.x, acc.y);
    __nv_bfloat162 h1 = __floats2bfloat162_rn(acc.z, acc.w);
    __nv_bfloat162 l0 = __floats2bfloat162_rn(acc.x - __bfloat162float(h0.x),
                                              acc.y - __bfloat162float(h0.y));
    __nv_bfloat162 l1 = __floats2bfloat162_rn(acc.z - __bfloat162float(h1.x),
                                              acc.w - __bfloat162float(h1.y));
    union U { uint2 u; __nv_bfloat162 h[2]; } uh, ul;
    uh.h[0] = h0; uh.h[1] = h1;
    ul.h[0] = l0; ul.h[1] = l1;
    ((uint2*)aggHi)[(size_t)node * 32 + lane] = uh.u;
    ((uint2*)aggLo)[(size_t)node * 32 + lane] = ul.u;
}

// ---------------- fused MLP: (agg @ W1 + b1).relu() @ W2 + b2 + epilogue -------
// GEMM1: A[256,128] @ W1^T -> h (stays in smem, bias+relu+bf16-split applied)
// GEMM2: h @ W2^T  -> epilogue
// EPI 1: relu(bn(v+b2)) + resid -> fp32 [M,128]
// EPI 2: log_softmax(v+b2) -> fp32 [M,64]  (fused via smem staging)
template<int NB2, int EPI>
__global__ __launch_bounds__(256, 1) void mlp_fused_kernel(
    const __nv_bfloat16* __restrict__ Ahi, const __nv_bfloat16* __restrict__ Alo,
    const __nv_bfloat16* __restrict__ B1hi, const __nv_bfloat16* __restrict__ B1lo,
    const __nv_bfloat16* __restrict__ B2hi, const __nv_bfloat16* __restrict__ B2lo,
    const float* __restrict__ bias1, const float* __restrict__ bias2,
    const float* __restrict__ gam, const float* __restrict__ bet,
    const float* __restrict__ mean, const float* __restrict__ var,
    const float* __restrict__ resid,
    float* __restrict__ outF, int M)
{
    extern __shared__ char smem[];
    constexpr int BM   = 256;
    constexpr int ROWB = 272;                 // 256B row + 16B pad
    constexpr int SM_PAR  = 0;                // b1[128], b2/sc/sh[128 each]
    constexpr int SM_A_HI = 2048;             // A tile, later h tile (hi)
    constexpr int SM_A_LO = SM_A_HI + BM * ROWB;
    constexpr int SM_B_HI = SM_A_LO + BM * ROWB;   // W1 then W2 (hi); later lsm stage
    constexpr int SM_B_LO = SM_B_HI + 128 * ROWB;
    constexpr int MI   = 4;                   // 4 x m16 = 64 rows per warp
    constexpr int NAT1 = 8;                   // GEMM1: WN=64
    constexpr int WN2  = NB2 / 2;
    constexpr int NAT2 = WN2 / 8;
    constexpr int LSTR = 65;                  // lsm staging row stride (floats)

    const uint32_t sb = smem_u32(smem);
    const int tid = threadIdx.x;
    const int wid = tid >> 5;
    const int lid = tid & 31;
    const int blockRow = blockIdx.x * BM;

    float* sB1 = (float*)(smem + SM_PAR);
    float* sB2 = sB1 + 128;
    float* sSc = sB2 + 128;
    float* sSh = sSc + 128;
    if (tid < 128) sB1[tid] = bias1[tid];
    if (tid < NB2) {
        sB2[tid] = bias2[tid];
        if (EPI == 1) {
            float s = gam[tid] * rsqrtf(var[tid] + 1e-5f);
            sSc[tid] = s;
            sSh[tid] = bet[tid] - mean[tid] * s;
        }
    }

    // ---- cp.async prologue: A (two K-halves) + W1 -----------------------------
    const uint4* AhiG = (const uint4*)Ahi;
    const uint4* AloG = (const uint4*)Alo;
    const uint4* B1hiG = (const uint4*)B1hi;
    const uint4* B1loG = (const uint4*)B1lo;
#pragma unroll
    for (int h = 0; h < 2; h++) {
        for (int idx = tid; idx < BM * 8; idx += 256) {
            int r = idx >> 3, c = (idx & 7) + h * 8;
            int gr = blockRow + r;
            int zf = (gr < M) ? 16 : 0;
            int grc = (gr < M) ? gr : 0;
            cp_async16(sb + SM_A_HI + r * ROWB + c * 16, AhiG + (size_t)grc * 16 + c, zf);
            cp_async16(sb + SM_A_LO + r * ROWB + c * 16, AloG + (size_t)grc * 16 + c, zf);
        }
        for (int idx = tid; idx < 128 * 8; idx += 256) {
            int r = idx >> 3, c = (idx & 7) + h * 8;
            cp_async16(sb + SM_B_HI + r * ROWB + c * 16, B1hiG + (size_t)r * 16 + c, 16);
            cp_async16(sb + SM_B_LO + r * ROWB + c * 16, B1loG + (size_t)r * 16 + c, 16);
        }
        cp_commit();
    }

    const int wm = wid & 3;              // 4 warp-rows x 64
    const int wn = wid >> 2;             // 2 warp-cols
    const int m0 = wm * 64;
    const int n0 = wn * 64;              // GEMM1 warp col base
    const int n02 = wn * WN2;            // GEMM2 warp col base

    const uint32_t aRow = (uint32_t)(lid & 15);
    const uint32_t aK   = (uint32_t)((lid >> 4) << 3);
    const uint32_t bN   = (uint32_t)((lid & 7) + ((lid >> 4) << 3));
    const uint32_t bK   = (uint32_t)(((lid >> 3) & 1) << 3);

    const uint32_t aHi0 = sb + SM_A_HI + (m0 + aRow) * ROWB + aK * 2;
    const uint32_t aLo0 = sb + SM_A_LO + (m0 + aRow) * ROWB + aK * 2;
    const uint32_t bHi1 = sb + SM_B_HI + (n0 + bN) * ROWB + bK * 2;
    const uint32_t bLo1 = sb + SM_B_LO + (n0 + bN) * ROWB + bK * 2;

    const int qr = lid >> 2;
    const int qc = (lid & 3) * 2;

    // ================= GEMM 1 =================
    float acc[MI][NAT1][4];
#pragma unroll
    for (int i = 0; i < MI; i++)
#pragma unroll
        for (int j = 0; j < NAT1; j++)
#pragma unroll
            for (int q = 0; q < 4; q++) acc[i][j][q] = 0.f;

#pragma unroll
    for (int half = 0; half < 2; half++) {
        if (half == 0) { cp_wait<1>(); } else { cp_wait<0>(); }
        __syncthreads();
#pragma unroll
        for (int ks = half * 4; ks < half * 4 + 4; ks++) {
            const uint32_t kb = (uint32_t)ks * 32;
            uint32_t ah[MI][4];
#pragma unroll
            for (int mi = 0; mi < MI; mi++)
                ldsm_x4(ah[mi], aHi0 + mi * 16 * ROWB + kb);
            uint32_t bh[NAT1][2], bl[NAT1][2];
#pragma unroll
            for (int jj = 0; jj < NAT1 / 2; jj++) {
                uint32_t r4[4];
                ldsm_x4(r4, bHi1 + jj * 16 * ROWB + kb);
                bh[2 * jj][0] = r4[0]; bh[2 * jj][1] = r4[1];
                bh[2 * jj + 1][0] = r4[2]; bh[2 * jj + 1][1] = r4[3];
                ldsm_x4(r4, bLo1 + jj * 16 * ROWB + kb);
                bl[2 * jj][0] = r4[0]; bl[2 * jj][1] = r4[1];
                bl[2 * jj + 1][0] = r4[2]; bl[2 * jj + 1][1] = r4[3];
            }
#pragma unroll
            for (int mi = 0; mi < MI; mi++)
#pragma unroll
                for (int j = 0; j < NAT1; j++) {
                    mma16816(acc[mi][j], ah[mi], bh[j]);
                    mma16816(acc[mi][j], ah[mi], bl[j]);
                }
            uint32_t al[MI][4];
#pragma unroll
            for (int mi = 0; mi < MI; mi++)
                ldsm_x4(al[mi], aLo0 + mi * 16 * ROWB + kb);
#pragma unroll
            for (int mi = 0; mi < MI; mi++)
#pragma unroll
                for (int j = 0; j < NAT1; j++)
                    mma16816(acc[mi][j], al[mi], bh[j]);
        }
    }
    __syncthreads();   // everyone done reading A and W1 smem

    // ---- load W2 into B region (overwrites W1) while we write h ---------------
    const uint4* B2hiG = (const uint4*)B2hi;
    const uint4* B2loG = (const uint4*)B2lo;
    for (int idx = tid; idx < NB2 * 16; idx += 256) {
        int r = idx >> 4, c = idx & 15;
        cp_async16(sb + SM_B_HI + r * ROWB + c * 16, B2hiG + (size_t)r * 16 + c, 16);
        cp_async16(sb + SM_B_LO + r * ROWB + c * 16, B2loG + (size_t)r * 16 + c, 16);
    }
    cp_commit();

    // ---- epilogue 1: h = relu(acc + b1), bf16-split, into A smem region -------
#pragma unroll
    for (int i = 0; i < MI; i++) {
        const int rl = m0 + i * 16 + qr;
#pragma unroll
        for (int j = 0; j < NAT1; j++) {
            const int col = n0 + j * 8 + qc;
            float t0 = fmaxf(acc[i][j][0] + sB1[col], 0.f);
            float t1 = fmaxf(acc[i][j][1] + sB1[col + 1], 0.f);
            float t2 = fmaxf(acc[i][j][2] + sB1[col], 0.f);
            float t3 = fmaxf(acc[i][j][3] + sB1[col + 1], 0.f);
            __nv_bfloat162 hh = __floats2bfloat162_rn(t0, t1);
            __nv_bfloat162 ll = __floats2bfloat162_rn(
                t0 - __bfloat162float(hh.x), t1 - __bfloat162float(hh.y));
            *(__nv_bfloat162*)(smem + SM_A_HI + rl * ROWB + col * 2) = hh;
            *(__nv_bfloat162*)(smem + SM_A_LO + rl * ROWB + col * 2) = ll;
            hh = __floats2bfloat162_rn(t2, t3);
            ll = __floats2bfloat162_rn(
                t2 - __bfloat162float(hh.x), t3 - __bfloat162float(hh.y));
            *(__nv_bfloat162*)(smem + SM_A_HI + (rl + 8) * ROWB + col * 2) = hh;
            *(__nv_bfloat162*)(smem + SM_A_LO + (rl + 8) * ROWB + col * 2) = ll;
        }
    }
    cp_wait<0>();
    __syncthreads();   // h writes + W2 arrival visible to all

    // ================= GEMM 2 =================
    float acc2[MI][NAT2][4];
#pragma unroll
    for (int i = 0; i < MI; i++)
#pragma unroll
        for (int j = 0; j < NAT2; j++)
#pragma unroll
            for (int q = 0; q < 4; q++) acc2[i][j][q] = 0.f;

    const uint32_t bHi2 = sb + SM_B_HI + (n02 + bN) * ROWB + bK * 2;
    const uint32_t bLo2 = sb + SM_B_LO + (n02 + bN) * ROWB + bK * 2;

#pragma unroll
    for (int ks = 0; ks < 8; ks++) {
        const uint32_t kb = (uint32_t)ks * 32;
        uint32_t ah[MI][4];
#pragma unroll
        for (int mi = 0; mi < MI; mi++)
            ldsm_x4(ah[mi], aHi0 + mi * 16 * ROWB + kb);
        uint32_t bh[NAT2][2], bl[NAT2][2];
#pragma unroll
        for (int jj = 0; jj < NAT2 / 2; jj++) {
            uint32_t r4[4];
            ldsm_x4(r4, bHi2 + jj * 16 * ROWB + kb);
            bh[2 * jj][0] = r4[0]; bh[2 * jj][1] = r4[1];
            bh[2 * jj + 1][0] = r4[2]; bh[2 * jj + 1][1] = r4[3];
            ldsm_x4(r4, bLo2 + jj * 16 * ROWB + kb);
            bl[2 * jj][0] = r4[0]; bl[2 * jj][1] = r4[1];
            bl[2 * jj + 1][0] = r4[2]; bl[2 * jj + 1][1] = r4[3];
        }
#pragma unroll
        for (int mi = 0; mi < MI; mi++)
#pragma unroll
            for (int j = 0; j < NAT2; j++) {
                mma16816(acc2[mi][j], ah[mi], bh[j]);
                mma16816(acc2[mi][j], ah[mi], bl[j]);
            }
        uint32_t al[MI][4];
#pragma unroll
        for (int mi = 0; mi < MI; mi++)
            ldsm_x4(al[mi], aLo0 + mi * 16 * ROWB + kb);
#pragma unroll
        for (int mi = 0; mi < MI; mi++)
#pragma unroll
            for (int j = 0; j < NAT2; j++)
                mma16816(acc2[mi][j], al[mi], bh[j]);
    }

    // ---- epilogue 2 ------------------------------------------------------------
    if (EPI == 1) {
#pragma unroll
        for (int i = 0; i < MI; i++) {
            const int r0 = blockRow + m0 + i * 16 + qr;   // rows r0, r0+8
#pragma unroll
            for (int j = 0; j < NAT2; j++) {
                const int col = n02 + j * 8 + qc;
                float t0 = acc2[i][j][0] + sB2[col];
                float t1 = acc2[i][j][1] + sB2[col + 1];
                float t2 = acc2[i][j][2] + sB2[col];
                float t3 = acc2[i][j][3] + sB2[col + 1];
                float sc0 = sSc[col], sc1 = sSc[col + 1];
                float sh0 = sSh[col], sh1 = sSh[col + 1];
                t0 = fmaxf(fmaf(t0, sc0, sh0), 0.f);
                t1 = fmaxf(fmaf(t1, sc1, sh1), 0.f);
                t2 = fmaxf(fmaf(t2, sc0, sh0), 0.f);
                t3 = fmaxf(fmaf(t3, sc1, sh1), 0.f);
                if (r0 < M) {
                    float2 rr = *(const float2*)(resid + (size_t)r0 * 128 + col);
                    *(float2*)(outF + (size_t)r0 * 128 + col) =
                        make_float2(t0 + rr.x, t1 + rr.y);
                }
                if (r0 + 8 < M) {
                    float2 rr = *(const float2*)(resid + (size_t)(r0 + 8) * 128 + col);
                    *(float2*)(outF + (size_t)(r0 + 8) * 128 + col) =
                        make_float2(t2 + rr.x, t3 + rr.y);
                }
            }
        }
    } else {
        // fused log_softmax: stage v into smem (reuse B region), reduce per row
        float* sL = (float*)(smem + SM_B_HI);
        __syncthreads();   // all GEMM2 B reads done before overwrite
#pragma unroll
        for (int i = 0; i < MI; i++) {
            const int rl = m0 + i * 16 + qr;
#pragma unroll
            for (int j = 0; j < NAT2; j++) {
                const int col = n02 + j * 8 + qc;
                sL[rl * LSTR + col]           = acc2[i][j][0] + sB2[col];
                sL[rl * LSTR + col + 1]       = acc2[i][j][1] + sB2[col + 1];
                sL[(rl + 8) * LSTR + col]     = acc2[i][j][2] + sB2[col];
                sL[(rl + 8) * LSTR + col + 1] = acc2[i][j][3] + sB2[col + 1];
            }
        }
        __syncthreads();
        const int grow = blockRow + tid;   // one thread per row
        if (grow < M) {
            float v[64];
            const float* row = sL + tid * LSTR;
#pragma unroll
            for (int c = 0; c < 64; c++) v[c] = row[c];
            float m = v[0];
#pragma unroll
            for (int c = 1; c < 64; c++) m = fmaxf(m, v[c]);
            float s = 0.f;
#pragma unroll
            for (int c = 0; c < 64; c++) s += expf(v[c] - m);
            float l = m + logf(s);
            float4* o4 = (float4*)(outF + (size_t)grow * 64);
#pragma unroll
            for (int q = 0; q < 16; q++)
                o4[q] = make_float4(v[4 * q] - l, v[4 * q + 1] - l,
                                    v[4 * q + 2] - l, v[4 * q + 3] - l);
        }
    }
}

// ---------------- launch ------------------------------------------------------
static inline int smem_total() {
    // params + A(2x 256x272) + B(2x 128x272)
    return 2048 + 2 * 256 * 272 + 2 * 128 * 272;
}

extern "C" void kernel_launch(void* const* d_in, const int* in_sizes, int n_in,
                              void* d_out, int out_size) {
    const float* x  = (const float*)d_in[0];
    const int*   ei = (const int*)d_in[1];
    const float* W1[3] = {(const float*)d_in[2],  (const float*)d_in[6],  (const float*)d_in[10]};
    const float* b1[3] = {(const float*)d_in[3],  (const float*)d_in[7],  (const float*)d_in[11]};
    const float* W2[3] = {(const float*)d_in[4],  (const float*)d_in[8],  (const float*)d_in[12]};
    const float* b2[3] = {(const float*)d_in[5],  (const float*)d_in[9],  (const float*)d_in[13]};
    const float* gg[2] = {(const float*)d_in[14], (const float*)d_in[18]};
    const float* be[2] = {(const float*)d_in[15], (const float*)d_in[19]};
    const float* mm[2] = {(const float*)d_in[16], (const float*)d_in[20]};
    const float* vv[2] = {(const float*)d_in[17], (const float*)d_in[21]};

    const int* src = ei;
    const int* dst = ei + GE;
    float* out = (float*)d_out;

    __nv_bfloat16 *aggHi, *aggLo, *wHi, *wLo;
    float *xA, *xB;
    int* degPtr;
    cudaGetSymbolAddress((void**)&aggHi, g_aggHi);
    cudaGetSymbolAddress((void**)&aggLo, g_aggLo);
    cudaGetSymbolAddress((void**)&wHi, g_wtHi);
    cudaGetSymbolAddress((void**)&wLo, g_wtLo);
    cudaGetSymbolAddress((void**)&xA, g_xA);
    cudaGetSymbolAddress((void**)&xB, g_xB);
    cudaGetSymbolAddress((void**)&degPtr, g_deg);

    const int SMT = smem_total();
    cudaFuncSetAttribute(mlp_fused_kernel<128, 1>,
                         cudaFuncAttributeMaxDynamicSharedMemorySize, SMT);
    cudaFuncSetAttribute(mlp_fused_kernel<64, 2>,
                         cudaFuncAttributeMaxDynamicSharedMemorySize, SMT);

    const int M = GN;
    const int gemmGrid = (GN + 255) / 256;           // 391
    const int warpGrid = (GN * 32 + 255) / 256;      // 12500
    const int SCAN_BLKS = (GN + 1023) / 1024;        // 98

    // Weight prep (single merged kernel)
    WPtrs wp;
    wp.w[0] = W1[0]; wp.w[1] = W2[0]; wp.w[2] = W1[1];
    wp.w[3] = W2[1]; wp.w[4] = W1[2]; wp.w[5] = W2[2];
    convw_all_kernel<<<704, 128>>>(wp, wHi, wLo);

    // CSR build (reused for all 3 layers; rowptr left shifted by fill)
    cudaMemsetAsync(degPtr, 0, GN * sizeof(int));
    count_deg_kernel<<<(GE / 4 + 255) / 256, 256>>>((const int4*)dst);
    scan1_kernel<<<SCAN_BLKS, 1024>>>();
    scan2_kernel<<<1, 128>>>();
    scan3_kernel<<<SCAN_BLKS, 1024>>>();
    fill_csr_kernel<<<(GE / 2 + 255) / 256, 256>>>((const int2*)src, (const int2*)dst);

    // Layer 0
    agg_kernel<<<warpGrid, 256>>>(x, aggHi, aggLo);
    mlp_fused_kernel<128, 1><<<gemmGrid, 256, SMT>>>(
        aggHi, aggLo,
        wHi + 0 * 16384, wLo + 0 * 16384, wHi + 1 * 16384, wLo + 1 * 16384,
        b1[0], b2[0], gg[0], be[0], mm[0], vv[0], x, xA, M);

    // Layer 1
    agg_kernel<<<warpGrid, 256>>>(xA, aggHi, aggLo);
    mlp_fused_kernel<128, 1><<<gemmGrid, 256, SMT>>>(
        aggHi, aggLo,
        wHi + 2 * 16384, wLo + 2 * 16384, wHi + 3 * 16384, wLo + 3 * 16384,
        b1[1], b2[1], gg[1], be[1], mm[1], vv[1], xA, xB, M);

    // Layer 2 (final conv + fused log_softmax)
    agg_kernel<<<warpGrid, 256>>>(xB, aggHi, aggLo);
    mlp_fused_kernel<64, 2><<<gemmGrid, 256, SMT>>>(
        aggHi, aggLo,
        wHi + 4 * 16384, wLo + 4 * 16384, wHi + 5 * 16384, wLo + 5 * 16384,
        b1[2], b2[2], 0, 0, 0, 0, 0, out, M);
}